// round 8
// baseline (speedup 1.0000x reference)
#include <cuda_runtime.h>
#include <cuda_bf16.h>

// Problem constants (fixed by the dataset)
#define B_COLS   64            // dense columns
#define N_MAX    50048         // neuron count (50000) rounded up a bit
#define NNZ_MAX  800000

// Scratch (no allocation allowed): ping-pong buffers + CSR row pointer
__device__ float g_bufX[N_MAX * B_COLS];
__device__ float g_bufY[N_MAX * B_COLS];
__device__ int   g_row_ptr[N_MAX + 1];

// ---------------------------------------------------------------------------
// Build CSR row_ptr from the sorted `rows` array.
// ---------------------------------------------------------------------------
__global__ void build_row_ptr_kernel(const int* __restrict__ rows, int nnz, int n,
                                     int* __restrict__ row_ptr) {
    int i = blockIdx.x * blockDim.x + threadIdx.x;
    if (i >= nnz) return;
    int r = rows[i];
    int rprev = (i == 0) ? -1 : rows[i - 1];
    for (int rr = rprev + 1; rr <= r; rr++) row_ptr[rr] = i;
    if (i == nnz - 1) {
        for (int rr = r + 1; rr <= n; rr++) row_ptr[rr] = nnz;
    }
}

// ---------------------------------------------------------------------------
// CSR SpMM: out[r, :] = sum_e vals[e] * x[cols[e], :]  (+ bias[r] if HAS_BIAS)
// One warp per row (grid-stride). Lane l owns dense cols {l, l+32}.
//
// Wavefront-rate fix (this round): the old float2 gather was ONE LDG.64
// producing 2 wavefronts, processed at the within-LDG replay rate of
// ~2.07 cyc/wf. Splitting into TWO LDG.32s (128B each, 1 wavefront each,
// +128B immediate offset) runs at the ~1.0 cyc/wf cross-LDG rate:
// 4.14 -> 2.0 cyc/edge of L1tex time for the same bytes.
// 4 edges/iter = 8 independent gathers in flight, 32-reg footprint
// (proven operating point: occ 100%, TLP does the latency hiding).
// ---------------------------------------------------------------------------
template <bool HAS_BIAS>
__global__ void __launch_bounds__(256, 8)
spmm_kernel(const float* __restrict__ vals, const int* __restrict__ cols,
            const int* __restrict__ row_ptr, const float* __restrict__ xin,
            const float* __restrict__ bias, float* __restrict__ out, int n) {
    const int lane   = threadIdx.x & 31;
    const int warpId = (blockIdx.x * blockDim.x + threadIdx.x) >> 5;
    const int nWarps = (gridDim.x * blockDim.x) >> 5;

    const float* __restrict__ xl = xin + lane;   // lane-offset base

    for (int row = warpId; row < n; row += nWarps) {
        int s = row_ptr[row];
        int e = row_ptr[row + 1];

        float acc0 = 0.0f, acc1 = 0.0f;   // cols l and l+32

        int k = s;
        // Peel to 4-edge alignment so float4/int4 metadata loads are 16B aligned.
        while (k < e && (k & 3)) {
            float v = vals[k];
            int   c = cols[k];
            const float* p = xl + c * B_COLS;
            float a = p[0];
            float b = p[32];
            acc0 = fmaf(v, a, acc0);
            acc1 = fmaf(v, b, acc1);
            k++;
        }

        // Main body: 4 edges/iter — 1 float4 + 1 int4 uniform metadata load,
        // 8 independent 128B (single-wavefront) gathers in flight.
        for (; k + 4 <= e; k += 4) {
            float4 v = *reinterpret_cast<const float4*>(vals + k);
            int4   c = *reinterpret_cast<const int4*>(cols + k);
            const float* p0 = xl + c.x * B_COLS;
            const float* p1 = xl + c.y * B_COLS;
            const float* p2 = xl + c.z * B_COLS;
            const float* p3 = xl + c.w * B_COLS;
            float a0 = p0[0], b0 = p0[32];
            float a1 = p1[0], b1 = p1[32];
            float a2 = p2[0], b2 = p2[32];
            float a3 = p3[0], b3 = p3[32];
            acc0 = fmaf(v.x, a0, acc0); acc1 = fmaf(v.x, b0, acc1);
            acc0 = fmaf(v.y, a1, acc0); acc1 = fmaf(v.y, b1, acc1);
            acc0 = fmaf(v.z, a2, acc0); acc1 = fmaf(v.z, b2, acc1);
            acc0 = fmaf(v.w, a3, acc0); acc1 = fmaf(v.w, b3, acc1);
        }

        // Scalar tail
        for (; k < e; k++) {
            float v = vals[k];
            int   c = cols[k];
            const float* p = xl + c * B_COLS;
            float a = p[0];
            float b = p[32];
            acc0 = fmaf(v, a, acc0);
            acc1 = fmaf(v, b, acc1);
        }

        if (HAS_BIAS) {
            float bb = bias[row];
            acc0 += bb; acc1 += bb;
        }
        out[row * B_COLS + lane]      = acc0;
        out[row * B_COLS + 32 + lane] = acc1;
    }
}

extern "C" void kernel_launch(void* const* d_in, const int* in_sizes, int n_in,
                              void* d_out, int out_size) {
    const float* x        = (const float*)d_in[0];   // [N, 64]
    const float* adj_vals = (const float*)d_in[1];   // [NNZ]
    const float* w_vals   = (const float*)d_in[2];   // [NNZ]
    const float* bias     = (const float*)d_in[3];   // [N]
    const int*   rows     = (const int*)d_in[4];     // [NNZ] sorted
    const int*   cols     = (const int*)d_in[5];     // [NNZ]
    // n_layers (d_in[6]) lives on device; the problem fixes it at 3.

    const int N   = in_sizes[0] / B_COLS;
    const int NNZ = in_sizes[1];

    float* bufX = nullptr; float* bufY = nullptr; int* row_ptr = nullptr;
    cudaGetSymbolAddress((void**)&bufX, g_bufX);
    cudaGetSymbolAddress((void**)&bufY, g_bufY);
    cudaGetSymbolAddress((void**)&row_ptr, g_row_ptr);

    float* outp = (float*)d_out;

    // 1) row_ptr
    {
        int threads = 256;
        int blocks = (NNZ + threads - 1) / threads;
        build_row_ptr_kernel<<<blocks, threads>>>(rows, NNZ, N, row_ptr);
    }

    // 2) three layers, two SpMMs each; last write goes to d_out.
    // One resident wave: 148 SMs x 8 blocks of 256 thr (32 regs cap).
    const int threads = 256;
    const int blocks  = 1184;

    // layer 1
    spmm_kernel<false><<<blocks, threads>>>(w_vals,   cols, row_ptr, x,    nullptr, bufY, N);
    spmm_kernel<true ><<<blocks, threads>>>(adj_vals, cols, row_ptr, bufY, bias,    bufX, N);
    // layer 2
    spmm_kernel<false><<<blocks, threads>>>(w_vals,   cols, row_ptr, bufX, nullptr, bufY, N);
    spmm_kernel<true ><<<blocks, threads>>>(adj_vals, cols, row_ptr, bufY, bias,    bufX, N);
    // layer 3
    spmm_kernel<false><<<blocks, threads>>>(w_vals,   cols, row_ptr, bufX, nullptr, bufY, N);
    spmm_kernel<true ><<<blocks, threads>>>(adj_vals, cols, row_ptr, bufY, bias,    outp, N);
}